// round 16
// baseline (speedup 1.0000x reference)
#include <cuda_runtime.h>
#include <cstdint>

#define S_  512
#define B_  64
#define C_  1024
#define V_  10
#define TS_ 128
#define K_  64            // chunk length
#define NQ_ (S_ / K_)     // 8 chunks
#define G_  8             // group size within chunk
#define LN_EPS_ 1e-5f

typedef unsigned long long ull;

// Scratch (allocation-free rule: __device__ globals)
__device__ float  g_P[(size_t)S_ * B_ * TS_];      // pos at step t [t][b][l] (16 MB)
__device__ float4 g_hd[(size_t)S_ * B_];           // (d0,d1,d2,w) per (t,b)
__device__ float  g_Gd[(size_t)B_ * NQ_ * 1024];   // per (b,q): diag[8][64] + off[7][64] (2 MB)
__device__ float  g_tape[(size_t)TS_ * B_ * C_];   // final tape [l][b][c] (32 MB)

// ---- packed fp32x2 helpers ----
__device__ __forceinline__ ull fma2(ull a, ull b, ull c) {
    ull d;
    asm("fma.rn.f32x2 %0, %1, %2, %3;" : "=l"(d) : "l"(a), "l"(b), "l"(c));
    return d;
}
__device__ __forceinline__ ull pk2(float lo, float hi) {
    ull r;
    asm("mov.b64 %0, {%1, %2};" : "=l"(r) : "f"(lo), "f"(hi));
    return r;
}
__device__ __forceinline__ float2 upk2(ull x) {
    float2 r;
    asm("mov.b64 {%0, %1}, %2;" : "=f"(r.x), "=f"(r.y) : "l"(x));
    return r;
}
__device__ __forceinline__ void cpa16(void* s, const void* g) {
    unsigned sa = (unsigned)__cvta_generic_to_shared(s);
    asm volatile("cp.async.ca.shared.global [%0], [%1], 16;" :: "r"(sa), "l"(g));
}
__device__ __forceinline__ void cpa_commit_waitall() {
    asm volatile("cp.async.commit_group;");
    asm volatile("cp.async.wait_group 0;" ::: "memory");
}

// ---------------------------------------------------------------------------
// Phase A: heads. dir = softmax(v@Wd^T+bd), w = sigmoid(v@Wr[1]+br[1]).
// ---------------------------------------------------------------------------
__global__ void __launch_bounds__(256) heads_kernel(
    const float* __restrict__ vals,
    const float* __restrict__ Wd, const float* __restrict__ bd,
    const float* __restrict__ Wr, const float* __restrict__ br)
{
    __shared__ float sW[4 * C_];
    int tid = threadIdx.x;
    for (int i = tid; i < 3 * C_; i += 256) sW[i] = Wd[i];
    for (int i = tid; i < C_;     i += 256) sW[3 * C_ + i] = Wr[C_ + i];
    __syncthreads();

    int wp = tid >> 5, lane = tid & 31;
    const float4* w4 = reinterpret_cast<const float4*>(sW);

    #pragma unroll 1
    for (int r = 0; r < 4; r++) {
        int row = blockIdx.x * 32 + wp * 4 + r;        // row = t*B + b
        const float4* v4 = reinterpret_cast<const float4*>(vals + (size_t)row * C_);

        float a0 = 0.f, a1 = 0.f, a2 = 0.f, a3 = 0.f;
        for (int i = lane; i < C_ / 4; i += 32) {
            float4 v = v4[i];
            float4 w;
            w = w4[i];       a0 += v.x*w.x + v.y*w.y + v.z*w.z + v.w*w.w;
            w = w4[256 + i]; a1 += v.x*w.x + v.y*w.y + v.z*w.z + v.w*w.w;
            w = w4[512 + i]; a2 += v.x*w.x + v.y*w.y + v.z*w.z + v.w*w.w;
            w = w4[768 + i]; a3 += v.x*w.x + v.y*w.y + v.z*w.z + v.w*w.w;
        }
        #pragma unroll
        for (int o = 16; o; o >>= 1) {
            a0 += __shfl_xor_sync(0xffffffffu, a0, o);
            a1 += __shfl_xor_sync(0xffffffffu, a1, o);
            a2 += __shfl_xor_sync(0xffffffffu, a2, o);
            a3 += __shfl_xor_sync(0xffffffffu, a3, o);
        }
        if (lane == 0) {
            float z0 = a0 + bd[0], z1 = a1 + bd[1], z2 = a2 + bd[2];
            float m  = fmaxf(z0, fmaxf(z1, z2));
            float e0 = expf(z0 - m), e1 = expf(z1 - m), e2 = expf(z2 - m);
            float inv = 1.f / (e0 + e1 + e2);
            float wg  = 1.f / (1.f + expf(-(a3 + br[1])));
            g_hd[row] = make_float4(e0 * inv, e1 * inv, e2 * inv, wg);
        }
    }
}

// ---------------------------------------------------------------------------
// Phase B: pos evolution. One warp per batch, depth-8 prefetch ring.
// ---------------------------------------------------------------------------
__global__ void __launch_bounds__(256) pos_kernel()
{
    int wp = threadIdx.x >> 5, lane = threadIdx.x & 31;
    int b = blockIdx.x * 8 + wp;
    float p0 = (lane == 0) ? 1.f : 0.f, p1 = 0.f, p2 = 0.f, p3 = 0.f;

    float4 D[8];
    #pragma unroll
    for (int k = 0; k < 8; k++) D[k] = g_hd[(size_t)k * B_ + b];

    for (int t = 0; t < S_; t += 8) {
        #pragma unroll
        for (int k = 0; k < 8; k++) {
            int tt = t + k;
            float4* dst = reinterpret_cast<float4*>(g_P + ((size_t)tt * B_ + b) * TS_);
            dst[lane] = make_float4(p0, p1, p2, p3);
            float4 Dk = D[k];
            D[k] = g_hd[(size_t)min(tt + 8, S_ - 1) * B_ + b];
            float d0 = Dk.x, d1 = Dk.y, d2 = Dk.z;
            float lw = __shfl_sync(0xffffffffu, p3, (lane + 31) & 31);
            float rw = __shfl_sync(0xffffffffu, p0, (lane + 1)  & 31);
            float n0 = p1 * d0 + p0 * d1 + lw * d2;
            float n1 = p2 * d0 + p1 * d1 + p0 * d2;
            float n2 = p3 * d0 + p2 * d1 + p1 * d2;
            float n3 = rw * d0 + p3 * d1 + p2 * d2;
            p0 = n0; p1 = n1; p2 = n2; p3 = n3;
        }
    }
}

// ---------------------------------------------------------------------------
// Phase B2: Gram blocks per (b,q): diag[g][jj][j] = p_{8g+jj}.p_{8g+j}
// and off[g][jj][j] = p_{8g+jj}.p_{8(g+1)+j} (g<7), both within chunk.
// ---------------------------------------------------------------------------
__global__ void __launch_bounds__(256) gramd_kernel()
{
    __shared__ float sPg[K_][132];
    int tid = threadIdx.x;
    int b = blockIdx.x >> 3, q = blockIdx.x & 7;
    int T0 = q * K_;

    for (int idx = tid; idx < K_ * TS_; idx += 256) {
        int t = idx >> 7, l = idx & 127;
        sPg[t][l] = g_P[((size_t)(T0 + t) * B_ + b) * TS_ + l];
    }
    __syncthreads();

    int w = tid >> 5, lane = tid & 31;   // warp w handles group w
    float* outd = g_Gd + (size_t)blockIdx.x * 1024 + w * 64;
    #pragma unroll
    for (int e = lane; e < 64; e += 32) {
        int jj = e >> 3, j = e & 7;
        const float* ra = sPg[w * 8 + jj];
        const float* rb = sPg[w * 8 + j];
        float d0 = 0.f, d1 = 0.f;
        #pragma unroll 8
        for (int k = 0; k < 32; k++) {
            float4 x = *reinterpret_cast<const float4*>(ra + 4 * k);
            float4 y = *reinterpret_cast<const float4*>(rb + 4 * k);
            d0 += x.x * y.x + x.y * y.y;
            d1 += x.z * y.z + x.w * y.w;
        }
        outd[e] = d0 + d1;
    }
    if (w < 7) {
        float* outo = g_Gd + (size_t)blockIdx.x * 1024 + 512 + w * 64;
        #pragma unroll
        for (int e = lane; e < 64; e += 32) {
            int jj = e >> 3, j = e & 7;
            const float* ra = sPg[w * 8 + jj];
            const float* rb = sPg[w * 8 + 8 + j];
            float d0 = 0.f, d1 = 0.f;
            #pragma unroll 8
            for (int k = 0; k < 32; k++) {
                float4 x = *reinterpret_cast<const float4*>(ra + 4 * k);
                float4 y = *reinterpret_cast<const float4*>(rb + 4 * k);
                d0 += x.x * y.x + x.y * y.y;
                d1 += x.z * y.z + x.w * y.w;
            }
            outo[e] = d0 + d1;
        }
    }
}

// ---- scan phase macros (verified instruction forms, parameterized by group) ----
#define PHASE1(GG)                                                              \
    {                                                                           \
        int t0p = (GG) * 8;                                                     \
        _Pragma("unroll 1")                                                     \
        for (int tl = 0; tl < 8; tl++) {                                        \
            const ulonglong2* pr = reinterpret_cast<const ulonglong2*>(         \
                sP + (t0p + tl) * TS_) + ty * 4;                                \
            ull a0 = 0ull, a1 = 0ull, a2 = 0ull, a3 = 0ull;                     \
            _Pragma("unroll")                                                   \
            for (int k = 0; k < 4; k++) {                                       \
                ulonglong2 p = pr[k];                                           \
                a0 = fma2(p.x, tp[2 * k][0], a0);                               \
                a1 = fma2(p.x, tp[2 * k][1], a1);                               \
                a2 = fma2(p.x, tp[2 * k][2], a2);                               \
                a3 = fma2(p.x, tp[2 * k][3], a3);                               \
                a0 = fma2(p.y, tp[2 * k + 1][0], a0);                           \
                a1 = fma2(p.y, tp[2 * k + 1][1], a1);                           \
                a2 = fma2(p.y, tp[2 * k + 1][2], a2);                           \
                a3 = fma2(p.y, tp[2 * k + 1][3], a3);                           \
            }                                                                   \
            float2 f0 = upk2(a0), f1 = upk2(a1), f2 = upk2(a2), f3 = upk2(a3);  \
            float4 st = make_float4(f0.x + f0.y, f1.x + f1.y,                   \
                                    f2.x + f2.y, f3.x + f3.y);                  \
            *reinterpret_cast<float4*>(spart + ((ty * 8 + tl) * TS_) + tx * 4) = st; \
        }                                                                       \
    }

#define PHASE3(GG)                                                              \
    {                                                                           \
        int t0p = (GG) * 8;                                                     \
        _Pragma("unroll 1")                                                     \
        for (int tl = 0; tl < 8; tl++) {                                        \
            const ulonglong2* pr = reinterpret_cast<const ulonglong2*>(         \
                sP + (t0p + tl) * TS_) + ty * 4;                                \
            float4 av = *reinterpret_cast<const float4*>(                       \
                sv + (t0p + tl) * TS_ + tx * 4);                                \
            ull b0 = pk2(av.x, av.x), b1 = pk2(av.y, av.y);                     \
            ull b2 = pk2(av.z, av.z), b3 = pk2(av.w, av.w);                     \
            _Pragma("unroll")                                                   \
            for (int k = 0; k < 4; k++) {                                       \
                ulonglong2 p = pr[k];                                           \
                tp[2 * k][0] = fma2(p.x, b0, tp[2 * k][0]);                     \
                tp[2 * k][1] = fma2(p.x, b1, tp[2 * k][1]);                     \
                tp[2 * k][2] = fma2(p.x, b2, tp[2 * k][2]);                     \
                tp[2 * k][3] = fma2(p.x, b3, tp[2 * k][3]);                     \
                tp[2 * k + 1][0] = fma2(p.y, b0, tp[2 * k + 1][0]);             \
                tp[2 * k + 1][1] = fma2(p.y, b1, tp[2 * k + 1][1]);             \
                tp[2 * k + 1][2] = fma2(p.y, b2, tp[2 * k + 1][2]);             \
                tp[2 * k + 1][3] = fma2(p.y, b3, tp[2 * k + 1][3]);             \
            }                                                                   \
        }                                                                       \
    }

// ---------------------------------------------------------------------------
// Phase C: chunked tape scan with the solve hidden under phase3.
// Per group g:  [solve(g) on tid<128  ||  phase3(g-1) on all warps] ; bar ;
//               phase1(g+1) ; bar.
// phase1(g+1) uses the tape missing group g; solve(g+1) corrects via the
// off-diagonal Gram block (a_{g} . off[g][.][t]). Chunk prologue does
// phase1(0) on the complete tape (no correction); epilogue does phase3(7).
// ---------------------------------------------------------------------------
__global__ void __launch_bounds__(256, 2) scan_kernel(const float* __restrict__ vals)
{
    extern __shared__ float sm[];
    float* sP    = sm;                   // [64][128]       8192 floats
    float* sv    = sP + K_ * TS_;        // [64][128]       8192 (v -> a)
    float* spart = sv + K_ * TS_;        // [ty8][tl8][128] 8192
    float* sGd   = spart + 8 * G_ * TS_; // diag 512 + off 448 + pad = 1024
    float* sw    = sGd + 1024;           // [64]

    int tid = threadIdx.x;
    int ty  = tid >> 5;                  // 0..7 slot group
    int tx  = tid & 31;                  // 0..31 channel group
    int b   = blockIdx.x >> 3;
    int cg  = blockIdx.x & 7;
    int c0  = cg << 7;

    // tape tile regs: tp[sp][c]: slot pair (ty*16+2sp, +1), channel tx*4+c
    ull tp[8][4];
    #pragma unroll
    for (int sp = 0; sp < 8; sp++)
        #pragma unroll
        for (int c = 0; c < 4; c++) tp[sp][c] = 0ull;

    for (int q = 0; q < NQ_; q++) {
        int T0 = q * K_;
        __syncthreads();   // protect sP/sv/sGd from previous chunk's readers
        // ---- stage P, v, Gd(diag+off), w ----
        #pragma unroll
        for (int i = 0; i < 8; i++) {
            int idx = tid + 256 * i;
            int t = idx >> 5, seg = idx & 31;
            cpa16(sP + t * TS_ + seg * 4,
                  g_P + ((size_t)(T0 + t) * B_ + b) * TS_ + seg * 4);
        }
        #pragma unroll
        for (int i = 0; i < 8; i++) {
            int idx = tid + 256 * i;
            int t = idx >> 5, seg = idx & 31;
            cpa16(sv + t * TS_ + seg * 4,
                  vals + ((size_t)(T0 + t) * B_ + b) * C_ + c0 + seg * 4);
        }
        cpa16(sGd + tid * 4, g_Gd + (size_t)(b * NQ_ + q) * 1024 + tid * 4);
        if (tid < K_)
            sw[tid] = g_hd[(size_t)(T0 + tid) * B_ + b].w;
        cpa_commit_waitall();
        __syncthreads();

        // ---- prologue: phase1 for group 0 (tape fully up to date) ----
        PHASE1(0);
        __syncthreads();

        for (int g = 0; g < G_; g++) {
            int t0 = g * 8;

            // ---- solve(g) (tid<128) overlapped with phase3(g-1) (all) ----
            if (tid < 128) {
                int c = tid;
                const float* Gg = sGd + g * 64;
                float at[8];
                #pragma unroll
                for (int j = 0; j < 8; j++) {
                    const float* pp = spart + j * TS_ + c;
                    float s01 = pp[0]        + pp[8  * TS_];
                    float s23 = pp[16 * TS_] + pp[24 * TS_];
                    float s45 = pp[32 * TS_] + pp[40 * TS_];
                    float s67 = pp[48 * TS_] + pp[56 * TS_];
                    float u = (s01 + s23) + (s45 + s67);
                    if (g > 0) {
                        const float* Go = sGd + 512 + (g - 1) * 64;
                        const float* ap = sv + (t0 - 8) * TS_ + c;
                        #pragma unroll
                        for (int jj = 0; jj < 8; jj++)
                            u += ap[jj * TS_] * Go[jj * 8 + j];
                    }
                    #pragma unroll
                    for (int jj = 0; jj < 8; jj++)
                        if (jj < j) u += at[jj] * Gg[jj * 8 + j];
                    float a = sw[t0 + j] * (sv[(t0 + j) * TS_ + c] - u);
                    at[j] = a;
                    sv[(t0 + j) * TS_ + c] = a;
                }
            }
            if (g > 0) PHASE3(g - 1);
            __syncthreads();

            if (g < G_ - 1) {
                PHASE1(g + 1);     // tape is T_{g-1}; solve(g+1) corrects
                __syncthreads();
            }
        }
        PHASE3(G_ - 1);
    }

    // ---- write final tape: coalesced STG.128 ----
    #pragma unroll
    for (int sp = 0; sp < 8; sp++) {
        float2 r0 = upk2(tp[sp][0]), r1 = upk2(tp[sp][1]);
        float2 r2 = upk2(tp[sp][2]), r3 = upk2(tp[sp][3]);
        int l0 = ty * 16 + 2 * sp;
        float4* d0 = reinterpret_cast<float4*>(
            g_tape + ((size_t)l0 * B_ + b) * C_ + c0 + tx * 4);
        float4* d1 = reinterpret_cast<float4*>(
            g_tape + ((size_t)(l0 + 1) * B_ + b) * C_ + c0 + tx * 4);
        *d0 = make_float4(r0.x, r1.x, r2.x, r3.x);
        *d1 = make_float4(r0.y, r1.y, r2.y, r3.y);
    }
}

// ---------------------------------------------------------------------------
// Phase D: LayerNorm + out = h @ Wo^T + bo. Warp-per-row, 4 rows per warp.
// ---------------------------------------------------------------------------
__global__ void __launch_bounds__(256) decode_kernel(
    const float* __restrict__ ln_g, const float* __restrict__ ln_b,
    const float* __restrict__ Wo,   const float* __restrict__ bo,
    float* __restrict__ out)
{
    __shared__ float sWo[V_ * C_];   // 40 KB
    int tid = threadIdx.x, lane = tid & 31, wp = tid >> 5;
    for (int i = tid; i < V_ * C_; i += 256) sWo[i] = Wo[i];
    __syncthreads();

    const float4* g4 = reinterpret_cast<const float4*>(ln_g);
    const float4* e4 = reinterpret_cast<const float4*>(ln_b);

    #pragma unroll 1
    for (int r = 0; r < 4; r++) {
        int row = blockIdx.x * 32 + wp * 4 + r;      // row = l*B + b
        const float4* src = reinterpret_cast<const float4*>(g_tape + (size_t)row * C_);
        float4 x[8];
        #pragma unroll
        for (int k = 0; k < 8; k++) x[k] = src[lane + 32 * k];

        float s = 0.f, qq = 0.f;
        #pragma unroll
        for (int k = 0; k < 8; k++) {
            s  += (x[k].x + x[k].y) + (x[k].z + x[k].w);
            qq += (x[k].x*x[k].x + x[k].y*x[k].y) + (x[k].z*x[k].z + x[k].w*x[k].w);
        }
        #pragma unroll
        for (int o = 16; o; o >>= 1) {
            s  += __shfl_xor_sync(0xffffffffu, s, o);
            qq += __shfl_xor_sync(0xffffffffu, qq, o);
        }
        float mu = s * (1.f / C_);
        float rstd = rsqrtf(qq * (1.f / C_) - mu * mu + LN_EPS_);

        #pragma unroll
        for (int k = 0; k < 8; k++) {
            float4 gg = g4[lane + 32 * k];
            float4 ee = e4[lane + 32 * k];
            x[k].x = (x[k].x - mu) * rstd * gg.x + ee.x;
            x[k].y = (x[k].y - mu) * rstd * gg.y + ee.y;
            x[k].z = (x[k].z - mu) * rstd * gg.z + ee.z;
            x[k].w = (x[k].w - mu) * rstd * gg.w + ee.w;
        }

        #pragma unroll
        for (int v = 0; v < V_; v++) {
            const float4* wv = reinterpret_cast<const float4*>(sWo + v * C_);
            float pp = 0.f;
            #pragma unroll
            for (int k = 0; k < 8; k++) {
                float4 w = wv[lane + 32 * k];
                pp += (x[k].x*w.x + x[k].y*w.y) + (x[k].z*w.z + x[k].w*w.w);
            }
            #pragma unroll
            for (int o = 16; o; o >>= 1) pp += __shfl_xor_sync(0xffffffffu, pp, o);
            if (lane == 0) out[(size_t)row * V_ + v] = pp + bo[v];
        }
    }
}

// ---------------------------------------------------------------------------
extern "C" void kernel_launch(void* const* d_in, const int* in_sizes, int n_in,
                              void* d_out, int out_size)
{
    const float* vals = (const float*)d_in[0];
    const float* Wd   = (const float*)d_in[1];
    const float* bd   = (const float*)d_in[2];
    const float* Wr   = (const float*)d_in[3];
    const float* br   = (const float*)d_in[4];
    const float* lng  = (const float*)d_in[5];
    const float* lnb  = (const float*)d_in[6];
    const float* Wo   = (const float*)d_in[7];
    const float* bo   = (const float*)d_in[8];
    float* out = (float*)d_out;

    const int SMEM_SCAN = (K_ * TS_ + K_ * TS_ + 8 * G_ * TS_ + 1024 + K_) * 4;
    cudaFuncSetAttribute(scan_kernel,
                         cudaFuncAttributeMaxDynamicSharedMemorySize, SMEM_SCAN);

    heads_kernel<<<(S_ * B_) / 32, 256>>>(vals, Wd, bd, Wr, br);
    pos_kernel<<<B_ / 8, 256>>>();
    gramd_kernel<<<B_ * NQ_, 256>>>();
    scan_kernel<<<B_ * (C_ / TS_), 256, SMEM_SCAN>>>(vals);
    decode_kernel<<<(TS_ * B_) / 32, 256>>>(lng, lnb, Wo, bo, out);
}